// round 2
// baseline (speedup 1.0000x reference)
#include <cuda_runtime.h>
#include <cuda_bf16.h>
#include <math.h>

// Problem dims (fixed by the dataset)
#define BB    2
#define LL    1024
#define NN    8
#define EE    512
#define HH    8
#define HD    64
#define E3    1536
#define MTOK  (BB * LL * NN)          // 16384 tokens

// ---------------------------------------------------------------------------
// Scratch (device globals: no runtime allocation allowed)
// ---------------------------------------------------------------------------
__device__ float g_qkv[(size_t)MTOK * E3];   // [token][1536]  (q | k | v)
__device__ float g_y  [(size_t)MTOK * EE];   // attention output, pre-proj

// ---------------------------------------------------------------------------
// SGEMM: C[M,Nn] = A[M,K] * W[K,Nn] + bias[Nn]
// 128x128 block, BK=8, 8x8 micro-tile, 256 threads.
// ---------------------------------------------------------------------------
#define GBM 128
#define GBN 128
#define GBK 8

__device__ __forceinline__ void sgemm_body(
    const float* __restrict__ A, const float* __restrict__ W,
    const float* __restrict__ bias, float* __restrict__ C,
    int M, int Nn, int K)
{
    __shared__ float As[GBK][GBM + 4];   // transposed A tile, padded
    __shared__ float Bs[GBK][GBN];

    const int tid  = threadIdx.x;           // 0..255
    const int tRow = tid >> 4;              // 0..15
    const int tCol = tid & 15;              // 0..15

    const float* Ab = A + (size_t)blockIdx.y * GBM * K;
    const float* Wb = W + (size_t)blockIdx.x * GBN;

    // load mapping
    const int aRow  = tid >> 1;             // 0..127
    const int aCol4 = (tid & 1) << 2;       // 0 or 4
    const int bRow  = tid >> 5;             // 0..7
    const int bCol4 = (tid & 31) << 2;      // 0..124

    float acc[8][8];
    #pragma unroll
    for (int i = 0; i < 8; i++)
        #pragma unroll
        for (int j = 0; j < 8; j++) acc[i][j] = 0.0f;

    for (int k0 = 0; k0 < K; k0 += GBK) {
        float4 av = *(const float4*)(Ab + (size_t)aRow * K + k0 + aCol4);
        float4 bv = *(const float4*)(Wb + (size_t)(k0 + bRow) * Nn + bCol4);
        As[aCol4 + 0][aRow] = av.x;
        As[aCol4 + 1][aRow] = av.y;
        As[aCol4 + 2][aRow] = av.z;
        As[aCol4 + 3][aRow] = av.w;
        *(float4*)&Bs[bRow][bCol4] = bv;
        __syncthreads();

        #pragma unroll
        for (int k = 0; k < GBK; k++) {
            float a[8], b[8];
            *(float4*)&a[0] = *(const float4*)&As[k][tRow * 8];
            *(float4*)&a[4] = *(const float4*)&As[k][tRow * 8 + 4];
            *(float4*)&b[0] = *(const float4*)&Bs[k][tCol * 8];
            *(float4*)&b[4] = *(const float4*)&Bs[k][tCol * 8 + 4];
            #pragma unroll
            for (int i = 0; i < 8; i++)
                #pragma unroll
                for (int j = 0; j < 8; j++)
                    acc[i][j] += a[i] * b[j];
        }
        __syncthreads();
    }

    const int gColBase = blockIdx.x * GBN + tCol * 8;
    float bsv[8];
    #pragma unroll
    for (int j = 0; j < 8; j++) bsv[j] = bias[gColBase + j];

    #pragma unroll
    for (int i = 0; i < 8; i++) {
        const int gRow = blockIdx.y * GBM + tRow * 8 + i;
        float4 o0, o1;
        o0.x = acc[i][0] + bsv[0]; o0.y = acc[i][1] + bsv[1];
        o0.z = acc[i][2] + bsv[2]; o0.w = acc[i][3] + bsv[3];
        o1.x = acc[i][4] + bsv[4]; o1.y = acc[i][5] + bsv[5];
        o1.z = acc[i][6] + bsv[6]; o1.w = acc[i][7] + bsv[7];
        *(float4*)(C + (size_t)gRow * Nn + gColBase)     = o0;
        *(float4*)(C + (size_t)gRow * Nn + gColBase + 4) = o1;
    }
}

__global__ __launch_bounds__(256) void qkv_gemm_kernel(
    const float* __restrict__ x, const float* __restrict__ w_attn,
    const float* __restrict__ b_attn)
{
    sgemm_body(x, w_attn, b_attn, g_qkv, MTOK, E3, EE);
}

__global__ __launch_bounds__(256) void proj_gemm_kernel(
    const float* __restrict__ w_proj, const float* __restrict__ b_proj,
    float* __restrict__ out)
{
    sgemm_body(g_y, w_proj, b_proj, out, MTOK, EE, EE);
}

// ---------------------------------------------------------------------------
// RoPE (in-place on q and k halves of g_qkv)
// one thread = one (token, head, freq j) -> touches q[j],q[j+32],k[j],k[j+32]
// ---------------------------------------------------------------------------
__global__ __launch_bounds__(256) void rope_kernel(const int* __restrict__ pos_ids)
{
    int idx = blockIdx.x * blockDim.x + threadIdx.x;
    if (idx >= MTOK * HH * 32) return;

    const int t   = idx >> 8;        // token 0..16383  (ordered (b,l,n))
    const int rem = idx & 255;
    const int h   = rem >> 5;        // 0..7
    const int j   = rem & 31;        // 0..31
    const int b   = t >> 13;         // t / (L*N)
    const int l   = (t >> 3) & (LL - 1);

    const float posf = (float)pos_ids[b * LL + l];
    // inv_freq = 10000^{-2j/64}
    const float inv_freq = powf(10000.0f, -(float)(2 * j) / (float)HD);
    const float ang = posf * inv_freq;
    float sn, cs;
    sincosf(ang, &sn, &cs);          // accurate range reduction (ang up to ~1023 rad)

    float* base = g_qkv + (size_t)t * E3 + h * HD;
    // q
    float q1 = base[j], q2 = base[j + 32];
    base[j]      = q1 * cs - q2 * sn;
    base[j + 32] = q2 * cs + q1 * sn;
    // k
    float k1 = base[512 + j], k2 = base[512 + j + 32];
    base[512 + j]      = k1 * cs - k2 * sn;
    base[512 + j + 32] = k2 * cs + k1 * sn;
}

// ---------------------------------------------------------------------------
// Flash attention (fp32, online softmax)
// grid: (qtile 0..15, bnh 0..127), 256 threads = 16x16 logical
// BQ=64 queries, BKV=32 keys per inner tile, hd=64
// ---------------------------------------------------------------------------
#define BQ  64
#define BKV 32

__global__ __launch_bounds__(256) void attn_kernel()
{
    __shared__ float Qs[BQ][HD + 4];        // 64x68, float4-aligned rows
    __shared__ float Ks[BKV][HD + 4];       // 32x68
    __shared__ float Vs[BKV][HD];           // 32x64
    __shared__ float Ss[BQ][BKV + 1];       // 64x33

    const int bnh = blockIdx.y;             // 0..127
    const int h   = bnh & 7;
    const int n   = (bnh >> 3) & 7;
    const int b   = bnh >> 6;
    const int qt  = blockIdx.x;             // 0..15

    const int tid = threadIdx.x;
    const int ty  = tid >> 4;               // 0..15 -> 4 query rows each
    const int tx  = tid & 15;               // 0..15

    // ---- load Q tile (64 rows x 64 dims) ----
    for (int i = tid; i < BQ * 16; i += 256) {
        const int r  = i >> 4;
        const int c4 = (i & 15) << 2;
        const size_t tok = (size_t)((b * LL + qt * BQ + r) * NN + n);
        float4 v = *(const float4*)(g_qkv + tok * E3 + h * HD + c4);
        *(float4*)&Qs[r][c4] = v;
    }

    float m_run[4], l_run[4], acc[4][4];
    #pragma unroll
    for (int i = 0; i < 4; i++) {
        m_run[i] = -1e30f; l_run[i] = 0.0f;
        #pragma unroll
        for (int j = 0; j < 4; j++) acc[i][j] = 0.0f;
    }

    const int nTiles = (qt + 1) * (BQ / BKV);   // causal: kv rows < (qt+1)*64

    for (int kt = 0; kt < nTiles; kt++) {
        __syncthreads();   // previous iter done with Ks/Vs/Ss (and Q writes on iter 0)

        // ---- load K,V tiles (32 rows x 64 dims each) ----
        for (int i = tid; i < BKV * 16; i += 256) {
            const int r  = i >> 4;
            const int c4 = (i & 15) << 2;
            const size_t tok  = (size_t)((b * LL + kt * BKV + r) * NN + n);
            const size_t base = tok * E3 + h * HD;
            *(float4*)&Ks[r][c4] = *(const float4*)(g_qkv + base + 512  + c4);
            *(float4*)&Vs[r][c4] = *(const float4*)(g_qkv + base + 1024 + c4);
        }
        __syncthreads();

        // ---- S = Q K^T : rows ty*4+i, cols tx*2+j ----
        float s[4][2] = {{0.f,0.f},{0.f,0.f},{0.f,0.f},{0.f,0.f}};
        #pragma unroll
        for (int kk = 0; kk < HD; kk += 4) {
            float4 a0 = *(const float4*)&Qs[ty * 4 + 0][kk];
            float4 a1 = *(const float4*)&Qs[ty * 4 + 1][kk];
            float4 a2 = *(const float4*)&Qs[ty * 4 + 2][kk];
            float4 a3 = *(const float4*)&Qs[ty * 4 + 3][kk];
            float4 b0 = *(const float4*)&Ks[tx * 2 + 0][kk];
            float4 b1 = *(const float4*)&Ks[tx * 2 + 1][kk];
            s[0][0] += a0.x*b0.x + a0.y*b0.y + a0.z*b0.z + a0.w*b0.w;
            s[0][1] += a0.x*b1.x + a0.y*b1.y + a0.z*b1.z + a0.w*b1.w;
            s[1][0] += a1.x*b0.x + a1.y*b0.y + a1.z*b0.z + a1.w*b0.w;
            s[1][1] += a1.x*b1.x + a1.y*b1.y + a1.z*b1.z + a1.w*b1.w;
            s[2][0] += a2.x*b0.x + a2.y*b0.y + a2.z*b0.z + a2.w*b0.w;
            s[2][1] += a2.x*b1.x + a2.y*b1.y + a2.z*b1.z + a2.w*b1.w;
            s[3][0] += a3.x*b0.x + a3.y*b0.y + a3.z*b0.z + a3.w*b0.w;
            s[3][1] += a3.x*b1.x + a3.y*b1.y + a3.z*b1.z + a3.w*b1.w;
        }

        // ---- mask + scale + online softmax ----
        const int qrBase = qt * BQ + ty * 4;
        const int kcBase = kt * BKV + tx * 2;
        #pragma unroll
        for (int i = 0; i < 4; i++) {
            #pragma unroll
            for (int j = 0; j < 2; j++) {
                if (kcBase + j > qrBase + i) s[i][j] = -1e30f;
                else                         s[i][j] *= 0.125f;  // 1/sqrt(64)
            }
        }

        #pragma unroll
        for (int i = 0; i < 4; i++) {
            float mt = fmaxf(s[i][0], s[i][1]);
            #pragma unroll
            for (int off = 1; off < 16; off <<= 1)
                mt = fmaxf(mt, __shfl_xor_sync(0xffffffffu, mt, off));
            const float mn = fmaxf(m_run[i], mt);
            const float al = __expf(m_run[i] - mn);
            const float p0 = __expf(s[i][0] - mn);
            const float p1 = __expf(s[i][1] - mn);
            float rs = p0 + p1;
            #pragma unroll
            for (int off = 1; off < 16; off <<= 1)
                rs += __shfl_xor_sync(0xffffffffu, rs, off);
            l_run[i] = l_run[i] * al + rs;
            m_run[i] = mn;
            #pragma unroll
            for (int j = 0; j < 4; j++) acc[i][j] *= al;
            Ss[ty * 4 + i][tx * 2 + 0] = p0;
            Ss[ty * 4 + i][tx * 2 + 1] = p1;
        }
        __syncthreads();

        // ---- O += P V : rows ty*4+i, cols tx*4+j ----
        #pragma unroll
        for (int kk = 0; kk < BKV; kk++) {
            float4 vb = *(const float4*)&Vs[kk][tx * 4];
            float p0 = Ss[ty * 4 + 0][kk];
            float p1 = Ss[ty * 4 + 1][kk];
            float p2 = Ss[ty * 4 + 2][kk];
            float p3 = Ss[ty * 4 + 3][kk];
            acc[0][0] += p0 * vb.x; acc[0][1] += p0 * vb.y; acc[0][2] += p0 * vb.z; acc[0][3] += p0 * vb.w;
            acc[1][0] += p1 * vb.x; acc[1][1] += p1 * vb.y; acc[1][2] += p1 * vb.z; acc[1][3] += p1 * vb.w;
            acc[2][0] += p2 * vb.x; acc[2][1] += p2 * vb.y; acc[2][2] += p2 * vb.z; acc[2][3] += p2 * vb.w;
            acc[3][0] += p3 * vb.x; acc[3][1] += p3 * vb.y; acc[3][2] += p3 * vb.z; acc[3][3] += p3 * vb.w;
        }
    }

    // ---- epilogue: normalize, write y ----
    #pragma unroll
    for (int i = 0; i < 4; i++) {
        const float inv = 1.0f / l_run[i];
        const int l = qt * BQ + ty * 4 + i;
        float4 o;
        o.x = acc[i][0] * inv; o.y = acc[i][1] * inv;
        o.z = acc[i][2] * inv; o.w = acc[i][3] * inv;
        *(float4*)(g_y + ((size_t)((b * LL + l) * NN + n)) * EE + h * HD + tx * 4) = o;
    }
}

// ---------------------------------------------------------------------------
// launch
// ---------------------------------------------------------------------------
extern "C" void kernel_launch(void* const* d_in, const int* in_sizes, int n_in,
                              void* d_out, int out_size)
{
    const float* x      = (const float*)d_in[0];
    const int*   pos    = (const int*)  d_in[1];
    const float* w_attn = (const float*)d_in[2];
    const float* b_attn = (const float*)d_in[3];
    const float* w_proj = (const float*)d_in[4];
    const float* b_proj = (const float*)d_in[5];
    float*       out    = (float*)d_out;

    // 1) QKV = x @ w_attn + b_attn      [16384 x 1536]
    qkv_gemm_kernel<<<dim3(E3 / GBN, MTOK / GBM), 256>>>(x, w_attn, b_attn);

    // 2) RoPE in-place on q,k
    rope_kernel<<<(MTOK * HH * 32) / 256, 256>>>(pos);

    // 3) causal flash attention -> g_y
    attn_kernel<<<dim3(LL / BQ, BB * NN * HH), 256>>>();

    // 4) out = y @ w_proj + b_proj      [16384 x 512]
    proj_gemm_kernel<<<dim3(EE / GBN, MTOK / GBM), 256>>>(w_proj, b_proj, out);
}

// round 4
// speedup vs baseline: 1.4303x; 1.4303x over previous
#include <cuda_runtime.h>
#include <math.h>
#include <stdint.h>

// Problem dims (fixed by the dataset)
#define BB    2
#define LL    1024
#define NN    8
#define EE    512
#define HH    8
#define HD    64
#define E3    1536
#define MTOK  (BB * LL * NN)          // 16384 tokens

// ---------------------------------------------------------------------------
// Scratch (device globals)
// ---------------------------------------------------------------------------
__device__ float g_qkv [(size_t)MTOK * E3];     // [token][1536] q|k|v (post-RoPE)
__device__ float g_y   [(size_t)MTOK * EE];     // attention out, pre-proj
__device__ float g_rope[(size_t)BB * LL * 64];  // [b*L+l][cos32|sin32]

// ---------------------------------------------------------------------------
// helpers
// ---------------------------------------------------------------------------
__device__ __forceinline__ float to_tf32(float x) {
    uint32_t o;
    asm("cvt.rna.tf32.f32 %0, %1;" : "=r"(o) : "f"(x));
    return __uint_as_float(o);
}

__device__ __forceinline__ void mma_tf32(float* c, const uint32_t* a,
                                         const uint32_t* b) {
    asm volatile(
        "mma.sync.aligned.m16n8k8.row.col.f32.tf32.tf32.f32 "
        "{%0,%1,%2,%3}, {%4,%5,%6,%7}, {%8,%9}, {%0,%1,%2,%3};"
        : "+f"(c[0]), "+f"(c[1]), "+f"(c[2]), "+f"(c[3])
        : "r"(a[0]), "r"(a[1]), "r"(a[2]), "r"(a[3]), "r"(b[0]), "r"(b[1]));
}

// ---------------------------------------------------------------------------
// mma.sync tf32 GEMM: C[128m x 128n] per CTA, 256 thr = 8 warps (4M x 2N),
// warp tile 32x64 (2 m-frags x 8 n-frags of m16n8k8). KC=32 smem chunks.
// Epilogue: +bias, optional fused RoPE (cols < 1024 of qkv), direct store.
// A [M,K] row-major; W [K,Nn] row-major.
// ---------------------------------------------------------------------------
#define KC   32
#define APAD 4
#define SAW  (128 + APAD)    // sA row pitch (k-major: sA[k][m])
#define SBW  (128 + APAD)    // sB row pitch (k-major: sB[k][n])

__device__ __forceinline__ void mma_gemm_body(
    const float* __restrict__ A, const float* __restrict__ W,
    const float* __restrict__ bias, float* __restrict__ C,
    int Nn, int K, bool do_rope)
{
    __shared__ float sA[KC][SAW];
    __shared__ float sB[KC][SBW];

    const int tid   = threadIdx.x;
    const int lane  = tid & 31;
    const int wid   = tid >> 5;
    const int warpM = wid & 3;          // 0..3 -> 32 rows each
    const int warpN = wid >> 2;         // 0..1 -> 64 cols each
    const int lq    = lane >> 2;        // 0..7
    const int lr    = lane & 3;         // 0..3

    const int m0 = blockIdx.y * 128;
    const int n0 = blockIdx.x * 128;

    float acc[2][8][4];
    #pragma unroll
    for (int i = 0; i < 2; i++)
        #pragma unroll
        for (int j = 0; j < 8; j++)
            #pragma unroll
            for (int c = 0; c < 4; c++) acc[i][j][c] = 0.0f;

    const int nchunks = K / KC;
    for (int ch = 0; ch < nchunks; ch++) {
        const int k0 = ch * KC;

        // ---- stage A: [128 rows x 32 k] -> sA[k][m] (transposed) ----
        #pragma unroll
        for (int it = 0; it < 4; it++) {
            const int i   = tid + it * 256;      // 0..1023
            const int row = i >> 3;              // 0..127
            const int kb  = (i & 7) << 2;        // 0,4,..,28
            float4 v = *(const float4*)(A + (size_t)(m0 + row) * K + k0 + kb);
            sA[kb + 0][row] = to_tf32(v.x);
            sA[kb + 1][row] = to_tf32(v.y);
            sA[kb + 2][row] = to_tf32(v.z);
            sA[kb + 3][row] = to_tf32(v.w);
        }
        // ---- stage B: W[k0..k0+31][n0..n0+127] -> sB[k][n] (natural) ----
        #pragma unroll
        for (int it = 0; it < 4; it++) {
            const int i  = tid + it * 256;
            const int kk = i >> 5;               // 0..31
            const int n4 = (i & 31) << 2;        // 0..124
            float4 v = *(const float4*)(W + (size_t)(k0 + kk) * Nn + n0 + n4);
            v.x = to_tf32(v.x); v.y = to_tf32(v.y);
            v.z = to_tf32(v.z); v.w = to_tf32(v.w);
            *(float4*)&sB[kk][n4] = v;
        }
        __syncthreads();

        // ---- compute: 4 k8 steps ----
        #pragma unroll
        for (int s = 0; s < KC / 8; s++) {
            const int s8 = s * 8;
            uint32_t af[2][4], bf[8][2];
            #pragma unroll
            for (int mf = 0; mf < 2; mf++) {
                const int mr = warpM * 32 + mf * 16;
                af[mf][0] = __float_as_uint(sA[s8 + lr    ][mr + lq    ]);
                af[mf][1] = __float_as_uint(sA[s8 + lr    ][mr + lq + 8]);
                af[mf][2] = __float_as_uint(sA[s8 + lr + 4][mr + lq    ]);
                af[mf][3] = __float_as_uint(sA[s8 + lr + 4][mr + lq + 8]);
            }
            #pragma unroll
            for (int nf = 0; nf < 8; nf++) {
                const int nb = warpN * 64 + nf * 8 + lq;
                bf[nf][0] = __float_as_uint(sB[s8 + lr    ][nb]);
                bf[nf][1] = __float_as_uint(sB[s8 + lr + 4][nb]);
            }
            #pragma unroll
            for (int mf = 0; mf < 2; mf++)
                #pragma unroll
                for (int nf = 0; nf < 8; nf++)
                    mma_tf32(acc[mf][nf], af[mf], bf[nf]);
        }
        __syncthreads();
    }

    // ---- epilogue: bias + optional RoPE + store ----
    const int gc0 = n0 + warpN * 64;    // head-aligned 64-col block
    const int q2  = lr * 2;

    float b0[8], b1[8];
    #pragma unroll
    for (int nf = 0; nf < 8; nf++) {
        b0[nf] = bias[gc0 + nf * 8 + q2];
        b1[nf] = bias[gc0 + nf * 8 + q2 + 1];
    }

    #pragma unroll
    for (int mf = 0; mf < 2; mf++) {
        #pragma unroll
        for (int rs = 0; rs < 2; rs++) {
            const int row = warpM * 32 + mf * 16 + lq + rs * 8;
            const int t   = m0 + row;
            float v[8][2];
            #pragma unroll
            for (int nf = 0; nf < 8; nf++) {
                v[nf][0] = acc[mf][nf][rs * 2]     + b0[nf];
                v[nf][1] = acc[mf][nf][rs * 2 + 1] + b1[nf];
            }
            if (do_rope && gc0 < 1024) {    // q:[0,512) k:[512,1024)
                const float* rt = g_rope +
                    (size_t)((t >> 13) * LL + ((t >> 3) & (LL - 1))) * 64;
                #pragma unroll
                for (int nf = 0; nf < 4; nf++) {
                    const int j = nf * 8 + q2;
                    const float cs0 = rt[j],     sn0 = rt[32 + j];
                    const float cs1 = rt[j + 1], sn1 = rt[33 + j];
                    const float x0 = v[nf][0], y0 = v[nf + 4][0];
                    const float x1 = v[nf][1], y1 = v[nf + 4][1];
                    v[nf][0]     = x0 * cs0 - y0 * sn0;
                    v[nf + 4][0] = y0 * cs0 + x0 * sn0;
                    v[nf][1]     = x1 * cs1 - y1 * sn1;
                    v[nf + 4][1] = y1 * cs1 + x1 * sn1;
                }
            }
            float* Crow = C + (size_t)t * Nn + gc0;
            #pragma unroll
            for (int nf = 0; nf < 8; nf++)
                *(float2*)(Crow + nf * 8 + q2) = make_float2(v[nf][0], v[nf][1]);
        }
    }
}

__global__ __launch_bounds__(256) void qkv_mma_kernel(
    const float* __restrict__ x, const float* __restrict__ w_attn,
    const float* __restrict__ b_attn)
{
    mma_gemm_body(x, w_attn, b_attn, g_qkv, E3, EE, true);
}

__global__ __launch_bounds__(256) void proj_mma_kernel(
    const float* __restrict__ w_proj, const float* __restrict__ b_proj,
    float* __restrict__ out)
{
    mma_gemm_body(g_y, w_proj, b_proj, out, EE, EE, false);
}

// ---------------------------------------------------------------------------
// RoPE cos/sin table: [b*L+l][cos j | sin j], j = 0..31
// ---------------------------------------------------------------------------
__global__ __launch_bounds__(256) void rope_table_kernel(const int* __restrict__ pos)
{
    const int i = blockIdx.x * blockDim.x + threadIdx.x;
    if (i >= BB * LL * 32) return;
    const int bl = i >> 5;
    const int j  = i & 31;
    const float p   = (float)pos[bl];
    const float inv = powf(10000.0f, -(float)j / 32.0f);
    float sn, cs;
    sincosf(p * inv, &sn, &cs);
    g_rope[(size_t)bl * 64 + j]      = cs;
    g_rope[(size_t)bl * 64 + 32 + j] = sn;
}

// ---------------------------------------------------------------------------
// Flash attention (fp32, online softmax) — unchanged from passing baseline
// ---------------------------------------------------------------------------
#define BQ  64
#define BKV 32

__global__ __launch_bounds__(256) void attn_kernel()
{
    __shared__ float Qs[BQ][HD + 4];
    __shared__ float Ks[BKV][HD + 4];
    __shared__ float Vs[BKV][HD];
    __shared__ float Ss[BQ][BKV + 1];

    const int bnh = blockIdx.y;
    const int h   = bnh & 7;
    const int n   = (bnh >> 3) & 7;
    const int b   = bnh >> 6;
    const int qt  = blockIdx.x;

    const int tid = threadIdx.x;
    const int ty  = tid >> 4;
    const int tx  = tid & 15;

    for (int i = tid; i < BQ * 16; i += 256) {
        const int r  = i >> 4;
        const int c4 = (i & 15) << 2;
        const size_t tok = (size_t)((b * LL + qt * BQ + r) * NN + n);
        float4 v = *(const float4*)(g_qkv + tok * E3 + h * HD + c4);
        *(float4*)&Qs[r][c4] = v;
    }

    float m_run[4], l_run[4], acc[4][4];
    #pragma unroll
    for (int i = 0; i < 4; i++) {
        m_run[i] = -1e30f; l_run[i] = 0.0f;
        #pragma unroll
        for (int j = 0; j < 4; j++) acc[i][j] = 0.0f;
    }

    const int nTiles = (qt + 1) * (BQ / BKV);

    for (int kt = 0; kt < nTiles; kt++) {
        __syncthreads();

        for (int i = tid; i < BKV * 16; i += 256) {
            const int r  = i >> 4;
            const int c4 = (i & 15) << 2;
            const size_t tok  = (size_t)((b * LL + kt * BKV + r) * NN + n);
            const size_t base = tok * E3 + h * HD;
            *(float4*)&Ks[r][c4] = *(const float4*)(g_qkv + base + 512  + c4);
            *(float4*)&Vs[r][c4] = *(const float4*)(g_qkv + base + 1024 + c4);
        }
        __syncthreads();

        float s[4][2] = {{0.f,0.f},{0.f,0.f},{0.f,0.f},{0.f,0.f}};
        #pragma unroll
        for (int kk = 0; kk < HD; kk += 4) {
            float4 a0 = *(const float4*)&Qs[ty * 4 + 0][kk];
            float4 a1 = *(const float4*)&Qs[ty * 4 + 1][kk];
            float4 a2 = *(const float4*)&Qs[ty * 4 + 2][kk];
            float4 a3 = *(const float4*)&Qs[ty * 4 + 3][kk];
            float4 b0 = *(const float4*)&Ks[tx * 2 + 0][kk];
            float4 b1 = *(const float4*)&Ks[tx * 2 + 1][kk];
            s[0][0] += a0.x*b0.x + a0.y*b0.y + a0.z*b0.z + a0.w*b0.w;
            s[0][1] += a0.x*b1.x + a0.y*b1.y + a0.z*b1.z + a0.w*b1.w;
            s[1][0] += a1.x*b0.x + a1.y*b0.y + a1.z*b0.z + a1.w*b0.w;
            s[1][1] += a1.x*b1.x + a1.y*b1.y + a1.z*b1.z + a1.w*b1.w;
            s[2][0] += a2.x*b0.x + a2.y*b0.y + a2.z*b0.z + a2.w*b0.w;
            s[2][1] += a2.x*b1.x + a2.y*b1.y + a2.z*b1.z + a2.w*b1.w;
            s[3][0] += a3.x*b0.x + a3.y*b0.y + a3.z*b0.z + a3.w*b0.w;
            s[3][1] += a3.x*b1.x + a3.y*b1.y + a3.z*b1.z + a3.w*b1.w;
        }

        const int qrBase = qt * BQ + ty * 4;
        const int kcBase = kt * BKV + tx * 2;
        #pragma unroll
        for (int i = 0; i < 4; i++) {
            #pragma unroll
            for (int j = 0; j < 2; j++) {
                if (kcBase + j > qrBase + i) s[i][j] = -1e30f;
                else                         s[i][j] *= 0.125f;
            }
        }

        #pragma unroll
        for (int i = 0; i < 4; i++) {
            float mt = fmaxf(s[i][0], s[i][1]);
            #pragma unroll
            for (int off = 1; off < 16; off <<= 1)
                mt = fmaxf(mt, __shfl_xor_sync(0xffffffffu, mt, off));
            const float mn = fmaxf(m_run[i], mt);
            const float al = __expf(m_run[i] - mn);
            const float p0 = __expf(s[i][0] - mn);
            const float p1 = __expf(s[i][1] - mn);
            float rs = p0 + p1;
            #pragma unroll
            for (int off = 1; off < 16; off <<= 1)
                rs += __shfl_xor_sync(0xffffffffu, rs, off);
            l_run[i] = l_run[i] * al + rs;
            m_run[i] = mn;
            #pragma unroll
            for (int j = 0; j < 4; j++) acc[i][j] *= al;
            Ss[ty * 4 + i][tx * 2 + 0] = p0;
            Ss[ty * 4 + i][tx * 2 + 1] = p1;
        }
        __syncthreads();

        #pragma unroll
        for (int kk = 0; kk < BKV; kk++) {
            float4 vb = *(const float4*)&Vs[kk][tx * 4];
            float p0 = Ss[ty * 4 + 0][kk];
            float p1 = Ss[ty * 4 + 1][kk];
            float p2 = Ss[ty * 4 + 2][kk];
            float p3 = Ss[ty * 4 + 3][kk];
            acc[0][0] += p0 * vb.x; acc[0][1] += p0 * vb.y; acc[0][2] += p0 * vb.z; acc[0][3] += p0 * vb.w;
            acc[1][0] += p1 * vb.x; acc[1][1] += p1 * vb.y; acc[1][2] += p1 * vb.z; acc[1][3] += p1 * vb.w;
            acc[2][0] += p2 * vb.x; acc[2][1] += p2 * vb.y; acc[2][2] += p2 * vb.z; acc[2][3] += p2 * vb.w;
            acc[3][0] += p3 * vb.x; acc[3][1] += p3 * vb.y; acc[3][2] += p3 * vb.z; acc[3][3] += p3 * vb.w;
        }
    }

    #pragma unroll
    for (int i = 0; i < 4; i++) {
        const float inv = 1.0f / l_run[i];
        const int l = qt * BQ + ty * 4 + i;
        float4 o;
        o.x = acc[i][0] * inv; o.y = acc[i][1] * inv;
        o.z = acc[i][2] * inv; o.w = acc[i][3] * inv;
        *(float4*)(g_y + ((size_t)((b * LL + l) * NN + n)) * EE + h * HD + tx * 4) = o;
    }
}

// ---------------------------------------------------------------------------
// launch
// ---------------------------------------------------------------------------
extern "C" void kernel_launch(void* const* d_in, const int* in_sizes, int n_in,
                              void* d_out, int out_size)
{
    const float* x      = (const float*)d_in[0];
    const int*   pos    = (const int*)  d_in[1];
    const float* w_attn = (const float*)d_in[2];
    const float* b_attn = (const float*)d_in[3];
    const float* w_proj = (const float*)d_in[4];
    const float* b_proj = (const float*)d_in[5];
    float*       out    = (float*)d_out;

    // 1) cos/sin table
    rope_table_kernel<<<(BB * LL * 32) / 256, 256>>>(pos);

    // 2) QKV tf32 mma.sync GEMM + fused bias + RoPE
    qkv_mma_kernel<<<dim3(E3 / 128, MTOK / 128), 256>>>(x, w_attn, b_attn);

    // 3) causal flash attention -> g_y
    attn_kernel<<<dim3(LL / BQ, BB * NN * HH), 256>>>();

    // 4) out = y @ w_proj + b_proj (tf32 mma.sync + bias)
    proj_mma_kernel<<<dim3(EE / 128, MTOK / 128), 256>>>(w_proj, b_proj, out);
}

// round 5
// speedup vs baseline: 2.6499x; 1.8526x over previous
#include <cuda_runtime.h>
#include <math.h>
#include <stdint.h>

// Problem dims (fixed by the dataset)
#define BB    2
#define LL    1024
#define NN    8
#define EE    512
#define HH    8
#define HD    64
#define E3    1536
#define MTOK  (BB * LL * NN)          // 16384 tokens

// ---------------------------------------------------------------------------
// Scratch (device globals)
// ---------------------------------------------------------------------------
__device__ float g_qkv [(size_t)MTOK * E3];     // [token][1536] q|k|v (post-RoPE)
__device__ float g_y   [(size_t)MTOK * EE];     // attention out, pre-proj
__device__ float g_rope[(size_t)BB * LL * 64];  // [b*L+l][cos32|sin32]

// ---------------------------------------------------------------------------
// helpers
// ---------------------------------------------------------------------------
__device__ __forceinline__ float to_tf32(float x) {
    uint32_t o;
    asm("cvt.rna.tf32.f32 %0, %1;" : "=r"(o) : "f"(x));
    return __uint_as_float(o);
}

__device__ __forceinline__ void mma_tf32(float* c, const uint32_t* a,
                                         const uint32_t* b) {
    asm volatile(
        "mma.sync.aligned.m16n8k8.row.col.f32.tf32.tf32.f32 "
        "{%0,%1,%2,%3}, {%4,%5,%6,%7}, {%8,%9}, {%0,%1,%2,%3};"
        : "+f"(c[0]), "+f"(c[1]), "+f"(c[2]), "+f"(c[3])
        : "r"(a[0]), "r"(a[1]), "r"(a[2]), "r"(a[3]), "r"(b[0]), "r"(b[1]));
}

// ---------------------------------------------------------------------------
// mma.sync tf32 GEMM: C[128m x 128n] per CTA, 256 thr = 8 warps (4M x 2N),
// warp tile 32x64 (2 m-frags x 8 n-frags of m16n8k8). KC=32 smem chunks.
// Epilogue: +bias, optional fused RoPE (cols < 1024 of qkv), direct store.
// A [M,K] row-major; W [K,Nn] row-major.    (unchanged from passing R4)
// ---------------------------------------------------------------------------
#define KC   32
#define APAD 4
#define SAW  (128 + APAD)
#define SBW  (128 + APAD)

__device__ __forceinline__ void mma_gemm_body(
    const float* __restrict__ A, const float* __restrict__ W,
    const float* __restrict__ bias, float* __restrict__ C,
    int Nn, int K, bool do_rope)
{
    __shared__ float sA[KC][SAW];
    __shared__ float sB[KC][SBW];

    const int tid   = threadIdx.x;
    const int lane  = tid & 31;
    const int wid   = tid >> 5;
    const int warpM = wid & 3;
    const int warpN = wid >> 2;
    const int lq    = lane >> 2;
    const int lr    = lane & 3;

    const int m0 = blockIdx.y * 128;
    const int n0 = blockIdx.x * 128;

    float acc[2][8][4];
    #pragma unroll
    for (int i = 0; i < 2; i++)
        #pragma unroll
        for (int j = 0; j < 8; j++)
            #pragma unroll
            for (int c = 0; c < 4; c++) acc[i][j][c] = 0.0f;

    const int nchunks = K / KC;
    for (int ch = 0; ch < nchunks; ch++) {
        const int k0 = ch * KC;

        #pragma unroll
        for (int it = 0; it < 4; it++) {
            const int i   = tid + it * 256;
            const int row = i >> 3;
            const int kb  = (i & 7) << 2;
            float4 v = *(const float4*)(A + (size_t)(m0 + row) * K + k0 + kb);
            sA[kb + 0][row] = to_tf32(v.x);
            sA[kb + 1][row] = to_tf32(v.y);
            sA[kb + 2][row] = to_tf32(v.z);
            sA[kb + 3][row] = to_tf32(v.w);
        }
        #pragma unroll
        for (int it = 0; it < 4; it++) {
            const int i  = tid + it * 256;
            const int kk = i >> 5;
            const int n4 = (i & 31) << 2;
            float4 v = *(const float4*)(W + (size_t)(k0 + kk) * Nn + n0 + n4);
            v.x = to_tf32(v.x); v.y = to_tf32(v.y);
            v.z = to_tf32(v.z); v.w = to_tf32(v.w);
            *(float4*)&sB[kk][n4] = v;
        }
        __syncthreads();

        #pragma unroll
        for (int s = 0; s < KC / 8; s++) {
            const int s8 = s * 8;
            uint32_t af[2][4], bf[8][2];
            #pragma unroll
            for (int mf = 0; mf < 2; mf++) {
                const int mr = warpM * 32 + mf * 16;
                af[mf][0] = __float_as_uint(sA[s8 + lr    ][mr + lq    ]);
                af[mf][1] = __float_as_uint(sA[s8 + lr    ][mr + lq + 8]);
                af[mf][2] = __float_as_uint(sA[s8 + lr + 4][mr + lq    ]);
                af[mf][3] = __float_as_uint(sA[s8 + lr + 4][mr + lq + 8]);
            }
            #pragma unroll
            for (int nf = 0; nf < 8; nf++) {
                const int nb = warpN * 64 + nf * 8 + lq;
                bf[nf][0] = __float_as_uint(sB[s8 + lr    ][nb]);
                bf[nf][1] = __float_as_uint(sB[s8 + lr + 4][nb]);
            }
            #pragma unroll
            for (int mf = 0; mf < 2; mf++)
                #pragma unroll
                for (int nf = 0; nf < 8; nf++)
                    mma_tf32(acc[mf][nf], af[mf], bf[nf]);
        }
        __syncthreads();
    }

    const int gc0 = n0 + warpN * 64;
    const int q2  = lr * 2;

    float b0[8], b1[8];
    #pragma unroll
    for (int nf = 0; nf < 8; nf++) {
        b0[nf] = bias[gc0 + nf * 8 + q2];
        b1[nf] = bias[gc0 + nf * 8 + q2 + 1];
    }

    #pragma unroll
    for (int mf = 0; mf < 2; mf++) {
        #pragma unroll
        for (int rs = 0; rs < 2; rs++) {
            const int row = warpM * 32 + mf * 16 + lq + rs * 8;
            const int t   = m0 + row;
            float v[8][2];
            #pragma unroll
            for (int nf = 0; nf < 8; nf++) {
                v[nf][0] = acc[mf][nf][rs * 2]     + b0[nf];
                v[nf][1] = acc[mf][nf][rs * 2 + 1] + b1[nf];
            }
            if (do_rope && gc0 < 1024) {
                const float* rt = g_rope +
                    (size_t)((t >> 13) * LL + ((t >> 3) & (LL - 1))) * 64;
                #pragma unroll
                for (int nf = 0; nf < 4; nf++) {
                    const int j = nf * 8 + q2;
                    const float cs0 = rt[j],     sn0 = rt[32 + j];
                    const float cs1 = rt[j + 1], sn1 = rt[33 + j];
                    const float x0 = v[nf][0], y0 = v[nf + 4][0];
                    const float x1 = v[nf][1], y1 = v[nf + 4][1];
                    v[nf][0]     = x0 * cs0 - y0 * sn0;
                    v[nf + 4][0] = y0 * cs0 + x0 * sn0;
                    v[nf][1]     = x1 * cs1 - y1 * sn1;
                    v[nf + 4][1] = y1 * cs1 + x1 * sn1;
                }
            }
            float* Crow = C + (size_t)t * Nn + gc0;
            #pragma unroll
            for (int nf = 0; nf < 8; nf++)
                *(float2*)(Crow + nf * 8 + q2) = make_float2(v[nf][0], v[nf][1]);
        }
    }
}

__global__ __launch_bounds__(256) void qkv_mma_kernel(
    const float* __restrict__ x, const float* __restrict__ w_attn,
    const float* __restrict__ b_attn)
{
    mma_gemm_body(x, w_attn, b_attn, g_qkv, E3, EE, true);
}

__global__ __launch_bounds__(256) void proj_mma_kernel(
    const float* __restrict__ w_proj, const float* __restrict__ b_proj,
    float* __restrict__ out)
{
    mma_gemm_body(g_y, w_proj, b_proj, out, EE, EE, false);
}

// ---------------------------------------------------------------------------
// RoPE cos/sin table: [b*L+l][cos j | sin j], j = 0..31
// ---------------------------------------------------------------------------
__global__ __launch_bounds__(256) void rope_table_kernel(const int* __restrict__ pos)
{
    const int i = blockIdx.x * blockDim.x + threadIdx.x;
    if (i >= BB * LL * 32) return;
    const int bl = i >> 5;
    const int j  = i & 31;
    const float p   = (float)pos[bl];
    const float inv = powf(10000.0f, -(float)j / 32.0f);
    float sn, cs;
    sincosf(p * inv, &sn, &cs);
    g_rope[(size_t)bl * 64 + j]      = cs;
    g_rope[(size_t)bl * 64 + 32 + j] = sn;
}

// ---------------------------------------------------------------------------
// Flash attention on tensor cores (tf32 mma.sync, online softmax)
// CTA: 128 threads = 4 warps; BQ=64 (warp w -> rows w*16..w*16+15), BKV=64.
// grid: (qt 0..15, bnh 0..127)
// smem: sKP holds K tile then is reused for P tile; sV holds Q (preloop), V.
// Pitches chosen so all fragment loads are bank-conflict-free:
//   sKP pitch 68: bank = 4*lq + lr (bijective over warp)
//   sV  pitch 72: bank = 8*lr + lq (bijective over warp)
// ---------------------------------------------------------------------------
#define ABQ 64
#define AKV 64
#define KP  68
#define VP  72

__global__ __launch_bounds__(128) void attn_mma_kernel()
{
    __shared__ float sKP[AKV][KP];   // K tile, then P tile   (17.0 KB)
    __shared__ float sV [AKV][VP];   // Q staging, then V     (18.0 KB)

    const int bnh  = blockIdx.y;
    const int h    = bnh & 7;
    const int n    = (bnh >> 3) & 7;
    const int b    = bnh >> 6;
    const int qt   = blockIdx.x;

    const int tid  = threadIdx.x;
    const int lane = tid & 31;
    const int wid  = tid >> 5;       // 0..3
    const int lq   = lane >> 2;      // 0..7
    const int lr   = lane & 3;       // 0..3
    const int w16  = wid * 16;

    // ---- stage Q (64x64, tf32) into sV ----
    for (int i = tid; i < ABQ * 16; i += 128) {
        const int r  = i >> 4;
        const int c4 = (i & 15) << 2;
        float4 v = *(const float4*)(g_qkv +
            ((size_t)((b * LL + qt * ABQ + r) * NN + n)) * E3 + h * HD + c4);
        v.x = to_tf32(v.x); v.y = to_tf32(v.y);
        v.z = to_tf32(v.z); v.w = to_tf32(v.w);
        *(float4*)&sV[r][c4] = v;
    }
    __syncthreads();

    // ---- preload Q fragments (reused for every kv tile) ----
    uint32_t aq[8][4];
    #pragma unroll
    for (int ks = 0; ks < 8; ks++) {
        const int k0 = ks * 8;
        aq[ks][0] = __float_as_uint(sV[w16 + lq    ][k0 + lr    ]);
        aq[ks][1] = __float_as_uint(sV[w16 + lq + 8][k0 + lr    ]);
        aq[ks][2] = __float_as_uint(sV[w16 + lq    ][k0 + lr + 4]);
        aq[ks][3] = __float_as_uint(sV[w16 + lq + 8][k0 + lr + 4]);
    }

    float m_run[2] = {-1e30f, -1e30f};
    float l_run[2] = {0.0f, 0.0f};
    float acc[8][4];
    #pragma unroll
    for (int nf = 0; nf < 8; nf++)
        #pragma unroll
        for (int c = 0; c < 4; c++) acc[nf][c] = 0.0f;

    const int nT = qt + 1;
    for (int kt = 0; kt < nT; kt++) {
        __syncthreads();   // prior-tile P/V reads (and Q frag preload) complete

        // ---- stage K -> sKP, V -> sV (tf32) ----
        for (int i = tid; i < AKV * 16; i += 128) {
            const int r  = i >> 4;
            const int c4 = (i & 15) << 2;
            const float* base = g_qkv +
                ((size_t)((b * LL + kt * AKV + r) * NN + n)) * E3 + h * HD;
            float4 kv = *(const float4*)(base + 512 + c4);
            float4 vv = *(const float4*)(base + 1024 + c4);
            kv.x = to_tf32(kv.x); kv.y = to_tf32(kv.y);
            kv.z = to_tf32(kv.z); kv.w = to_tf32(kv.w);
            vv.x = to_tf32(vv.x); vv.y = to_tf32(vv.y);
            vv.z = to_tf32(vv.z); vv.w = to_tf32(vv.w);
            *(float4*)&sKP[r][c4] = kv;
            *(float4*)&sV [r][c4] = vv;
        }
        __syncthreads();

        // ---- S = Q K^T  (warp rows w16.., all 64 kv cols) ----
        float s[8][4];
        #pragma unroll
        for (int nf = 0; nf < 8; nf++)
            #pragma unroll
            for (int c = 0; c < 4; c++) s[nf][c] = 0.0f;

        #pragma unroll
        for (int ks = 0; ks < 8; ks++) {
            const int k0 = ks * 8;
            #pragma unroll
            for (int nf = 0; nf < 8; nf++) {
                uint32_t bb[2];
                bb[0] = __float_as_uint(sKP[nf * 8 + lq][k0 + lr    ]);
                bb[1] = __float_as_uint(sKP[nf * 8 + lq][k0 + lr + 4]);
                mma_tf32(s[nf], aq[ks], bb);
            }
        }
        __syncthreads();   // all warps done reading K before P overwrites sKP

        // ---- scale + causal mask (only diagonal tile needs masking) ----
        const bool diag = (kt == qt);
        const int  r0l  = w16 + lq;       // local row of c0/c1
        const int  r1l  = r0l + 8;        // local row of c2/c3
        float mx0 = -1e30f, mx1 = -1e30f;
        #pragma unroll
        for (int nf = 0; nf < 8; nf++) {
            #pragma unroll
            for (int c = 0; c < 2; c++) {
                const int col = nf * 8 + 2 * lr + c;
                float v0 = s[nf][c]     * 0.125f;
                float v1 = s[nf][2 + c] * 0.125f;
                if (diag && col > r0l) v0 = -1e30f;
                if (diag && col > r1l) v1 = -1e30f;
                s[nf][c]     = v0;
                s[nf][2 + c] = v1;
                mx0 = fmaxf(mx0, v0);
                mx1 = fmaxf(mx1, v1);
            }
        }
        #pragma unroll
        for (int off = 1; off < 4; off <<= 1) {
            mx0 = fmaxf(mx0, __shfl_xor_sync(0xffffffffu, mx0, off));
            mx1 = fmaxf(mx1, __shfl_xor_sync(0xffffffffu, mx1, off));
        }

        const float mn0 = fmaxf(m_run[0], mx0);
        const float mn1 = fmaxf(m_run[1], mx1);
        const float al0 = __expf(m_run[0] - mn0);
        const float al1 = __expf(m_run[1] - mn1);
        m_run[0] = mn0; m_run[1] = mn1;

        float sum0 = 0.0f, sum1 = 0.0f;
        #pragma unroll
        for (int nf = 0; nf < 8; nf++) {
            const float p00 = __expf(s[nf][0] - mn0);
            const float p01 = __expf(s[nf][1] - mn0);
            const float p10 = __expf(s[nf][2] - mn1);
            const float p11 = __expf(s[nf][3] - mn1);
            sum0 += p00 + p01;
            sum1 += p10 + p11;
            const int cc = nf * 8 + 2 * lr;
            sKP[r0l][cc]     = to_tf32(p00);
            sKP[r0l][cc + 1] = to_tf32(p01);
            sKP[r1l][cc]     = to_tf32(p10);
            sKP[r1l][cc + 1] = to_tf32(p11);
        }
        #pragma unroll
        for (int off = 1; off < 4; off <<= 1) {
            sum0 += __shfl_xor_sync(0xffffffffu, sum0, off);
            sum1 += __shfl_xor_sync(0xffffffffu, sum1, off);
        }
        l_run[0] = l_run[0] * al0 + sum0;
        l_run[1] = l_run[1] * al1 + sum1;

        #pragma unroll
        for (int nf = 0; nf < 8; nf++) {
            acc[nf][0] *= al0; acc[nf][1] *= al0;
            acc[nf][2] *= al1; acc[nf][3] *= al1;
        }
        __syncwarp();      // P rows are warp-private: warp-level sync suffices

        // ---- O += P V ----
        #pragma unroll
        for (int ks = 0; ks < 8; ks++) {
            const int k0 = ks * 8;
            uint32_t ap[4];
            ap[0] = __float_as_uint(sKP[r0l][k0 + lr    ]);
            ap[1] = __float_as_uint(sKP[r1l][k0 + lr    ]);
            ap[2] = __float_as_uint(sKP[r0l][k0 + lr + 4]);
            ap[3] = __float_as_uint(sKP[r1l][k0 + lr + 4]);
            #pragma unroll
            for (int nf = 0; nf < 8; nf++) {
                uint32_t bb[2];
                bb[0] = __float_as_uint(sV[k0 + lr    ][nf * 8 + lq]);
                bb[1] = __float_as_uint(sV[k0 + lr + 4][nf * 8 + lq]);
                mma_tf32(acc[nf], ap, bb);
            }
        }
    }

    // ---- epilogue: normalize + store ----
    const float inv0 = 1.0f / l_run[0];
    const float inv1 = 1.0f / l_run[1];
    const int gr0 = qt * ABQ + w16 + lq;
    const int gr1 = gr0 + 8;
    float* y0 = g_y + ((size_t)((b * LL + gr0) * NN + n)) * EE + h * HD;
    float* y1 = g_y + ((size_t)((b * LL + gr1) * NN + n)) * EE + h * HD;
    #pragma unroll
    for (int nf = 0; nf < 8; nf++) {
        const int cc = nf * 8 + 2 * lr;
        *(float2*)(y0 + cc) = make_float2(acc[nf][0] * inv0, acc[nf][1] * inv0);
        *(float2*)(y1 + cc) = make_float2(acc[nf][2] * inv1, acc[nf][3] * inv1);
    }
}

// ---------------------------------------------------------------------------
// launch
// ---------------------------------------------------------------------------
extern "C" void kernel_launch(void* const* d_in, const int* in_sizes, int n_in,
                              void* d_out, int out_size)
{
    const float* x      = (const float*)d_in[0];
    const int*   pos    = (const int*)  d_in[1];
    const float* w_attn = (const float*)d_in[2];
    const float* b_attn = (const float*)d_in[3];
    const float* w_proj = (const float*)d_in[4];
    const float* b_proj = (const float*)d_in[5];
    float*       out    = (float*)d_out;

    // 1) cos/sin table
    rope_table_kernel<<<(BB * LL * 32) / 256, 256>>>(pos);

    // 2) QKV tf32 mma.sync GEMM + fused bias + RoPE
    qkv_mma_kernel<<<dim3(E3 / 128, MTOK / 128), 256>>>(x, w_attn, b_attn);

    // 3) causal flash attention on tensor cores -> g_y
    attn_mma_kernel<<<dim3(LL / ABQ, BB * NN * HH), 128>>>();

    // 4) out = y @ w_proj + b_proj (tf32 mma.sync + bias)
    proj_mma_kernel<<<dim3(EE / 128, MTOK / 128), 256>>>(w_proj, b_proj, out);
}

// round 7
// speedup vs baseline: 3.0342x; 1.1451x over previous
#include <cuda_runtime.h>
#include <math.h>
#include <stdint.h>

// Problem dims (fixed by the dataset)
#define BB    2
#define LL    1024
#define NN    8
#define EE    512
#define HH    8
#define HD    64
#define E3    1536
#define MTOK  (BB * LL * NN)          // 16384 tokens

// ---------------------------------------------------------------------------
// Scratch (device globals)
// ---------------------------------------------------------------------------
__device__ float g_qkv [(size_t)MTOK * E3];     // [token][1536] q|k|v (tf32, post-RoPE)
__device__ float g_y   [(size_t)MTOK * EE];     // attention out (tf32)
__device__ float g_rope[(size_t)BB * LL * 64];  // [b*L+l][cos32|sin32]
__device__ float g_x   [(size_t)MTOK * EE];     // x pre-rounded to tf32
__device__ float g_wa  [(size_t)EE * E3];       // w_attn tf32
__device__ float g_wp  [(size_t)EE * EE];       // w_proj tf32

// ---------------------------------------------------------------------------
// helpers
// ---------------------------------------------------------------------------
__device__ __forceinline__ float to_tf32(float x) {
    uint32_t o;
    asm("cvt.rna.tf32.f32 %0, %1;" : "=r"(o) : "f"(x));
    return __uint_as_float(o);
}

__device__ __forceinline__ void mma_tf32(float* c, const uint32_t* a,
                                         const uint32_t* b) {
    asm volatile(
        "mma.sync.aligned.m16n8k8.row.col.f32.tf32.tf32.f32 "
        "{%0,%1,%2,%3}, {%4,%5,%6,%7}, {%8,%9}, {%0,%1,%2,%3};"
        : "+f"(c[0]), "+f"(c[1]), "+f"(c[2]), "+f"(c[3])
        : "r"(a[0]), "r"(a[1]), "r"(a[2]), "r"(a[3]), "r"(b[0]), "r"(b[1]));
}

__device__ __forceinline__ void cp16(void* smem, const void* gmem) {
    uint32_t s = (uint32_t)__cvta_generic_to_shared(smem);
    asm volatile("cp.async.ca.shared.global [%0], [%1], 16;" :: "r"(s), "l"(gmem));
}
#define CP_COMMIT() asm volatile("cp.async.commit_group;" ::)
#define CP_WAIT1()  asm volatile("cp.async.wait_group 1;" ::: "memory")

// ---------------------------------------------------------------------------
// elementwise tf32 pre-rounding (write __device__ symbols directly: no
// cudaGetSymbolAddress on the host side)
// ---------------------------------------------------------------------------
__device__ __forceinline__ void cvt_body(const float* __restrict__ s,
                                         float* __restrict__ d, int n)
{
    const int i = (blockIdx.x * blockDim.x + threadIdx.x) << 2;
    if (i >= n) return;
    float4 v = *(const float4*)(s + i);
    v.x = to_tf32(v.x); v.y = to_tf32(v.y);
    v.z = to_tf32(v.z); v.w = to_tf32(v.w);
    *(float4*)(d + i) = v;
}
__global__ __launch_bounds__(256) void cvt_x_kernel (const float* __restrict__ s)
{ cvt_body(s, g_x,  MTOK * EE); }
__global__ __launch_bounds__(256) void cvt_wa_kernel(const float* __restrict__ s)
{ cvt_body(s, g_wa, EE * E3); }
__global__ __launch_bounds__(256) void cvt_wp_kernel(const float* __restrict__ s)
{ cvt_body(s, g_wp, EE * EE); }

// ---------------------------------------------------------------------------
// cp.async double-buffered tf32 GEMM: C[128m x 128n] per CTA.
// 256 thr = 8 warps (4M x 2N), warp 32x64 (2x8 m16n8k8 frags), KC=16/stage.
// Inputs A,W already tf32-rounded. Epilogue: +bias, opt RoPE, opt tf32 store.
//   sA[st][row][k]: pitch 20 -> frag bank = (20*lq+lr)%32 bijective, no conflict
//   sB[st][k][n]:   pitch 132 -> conflict-free as in R4/R5
// ---------------------------------------------------------------------------
#define KC2 16
#define PA  20
#define PB  132

__device__ __forceinline__ void gemm_v2(
    const float* __restrict__ A, const float* __restrict__ W,
    const float* __restrict__ bias, float* __restrict__ C,
    int Nn, int K, bool do_rope, bool round_store)
{
    __shared__ float sA[2][128][PA];   // 20.0 KB
    __shared__ float sB[2][KC2][PB];   // 16.5 KB

    const int tid   = threadIdx.x;
    const int lane  = tid & 31;
    const int wid   = tid >> 5;
    const int warpM = wid & 3;
    const int warpN = wid >> 2;
    const int lq    = lane >> 2;
    const int lr    = lane & 3;

    const int m0 = blockIdx.y * 128;
    const int n0 = blockIdx.x * 128;

    float acc[2][8][4];
    #pragma unroll
    for (int i = 0; i < 2; i++)
        #pragma unroll
        for (int j = 0; j < 8; j++)
            #pragma unroll
            for (int c = 0; c < 4; c++) acc[i][j][c] = 0.0f;

    const int nch = K / KC2;

    // ---- prefetch stage 0 ----
    {
        #pragma unroll
        for (int it = 0; it < 2; it++) {
            const int i   = tid + it * 256;     // 0..511
            const int row = i >> 2;
            const int c4  = (i & 3) << 2;
            cp16(&sA[0][row][c4], A + (size_t)(m0 + row) * K + c4);
        }
        #pragma unroll
        for (int it = 0; it < 2; it++) {
            const int i  = tid + it * 256;
            const int kk = i >> 5;
            const int n4 = (i & 31) << 2;
            cp16(&sB[0][kk][n4], W + (size_t)kk * Nn + n0 + n4);
        }
        CP_COMMIT();
    }

    for (int ch = 0; ch < nch; ch++) {
        // ---- prefetch next stage (possibly empty group) ----
        if (ch + 1 < nch) {
            const int st = (ch + 1) & 1;
            const int k0 = (ch + 1) * KC2;
            #pragma unroll
            for (int it = 0; it < 2; it++) {
                const int i   = tid + it * 256;
                const int row = i >> 2;
                const int c4  = (i & 3) << 2;
                cp16(&sA[st][row][c4], A + (size_t)(m0 + row) * K + k0 + c4);
            }
            #pragma unroll
            for (int it = 0; it < 2; it++) {
                const int i  = tid + it * 256;
                const int kk = i >> 5;
                const int n4 = (i & 31) << 2;
                cp16(&sB[st][kk][n4], W + (size_t)(k0 + kk) * Nn + n0 + n4);
            }
        }
        CP_COMMIT();
        CP_WAIT1();            // stage ch resident
        __syncthreads();

        const int st = ch & 1;
        #pragma unroll
        for (int s = 0; s < 2; s++) {
            const int s8 = s * 8;
            uint32_t af[2][4], bf[8][2];
            #pragma unroll
            for (int mf = 0; mf < 2; mf++) {
                const int mr = warpM * 32 + mf * 16;
                af[mf][0] = __float_as_uint(sA[st][mr + lq    ][s8 + lr    ]);
                af[mf][1] = __float_as_uint(sA[st][mr + lq + 8][s8 + lr    ]);
                af[mf][2] = __float_as_uint(sA[st][mr + lq    ][s8 + lr + 4]);
                af[mf][3] = __float_as_uint(sA[st][mr + lq + 8][s8 + lr + 4]);
            }
            #pragma unroll
            for (int nf = 0; nf < 8; nf++) {
                const int nb = warpN * 64 + nf * 8 + lq;
                bf[nf][0] = __float_as_uint(sB[st][s8 + lr    ][nb]);
                bf[nf][1] = __float_as_uint(sB[st][s8 + lr + 4][nb]);
            }
            #pragma unroll
            for (int mf = 0; mf < 2; mf++)
                #pragma unroll
                for (int nf = 0; nf < 8; nf++)
                    mma_tf32(acc[mf][nf], af[mf], bf[nf]);
        }
        __syncthreads();       // all warps done before buffer reuse
    }

    // ---- epilogue ----
    const int gc0 = n0 + warpN * 64;
    const int q2  = lr * 2;

    float b0[8], b1[8];
    #pragma unroll
    for (int nf = 0; nf < 8; nf++) {
        b0[nf] = bias[gc0 + nf * 8 + q2];
        b1[nf] = bias[gc0 + nf * 8 + q2 + 1];
    }

    #pragma unroll
    for (int mf = 0; mf < 2; mf++) {
        #pragma unroll
        for (int rs = 0; rs < 2; rs++) {
            const int row = warpM * 32 + mf * 16 + lq + rs * 8;
            const int t   = m0 + row;
            float v[8][2];
            #pragma unroll
            for (int nf = 0; nf < 8; nf++) {
                v[nf][0] = acc[mf][nf][rs * 2]     + b0[nf];
                v[nf][1] = acc[mf][nf][rs * 2 + 1] + b1[nf];
            }
            if (do_rope && gc0 < 1024) {    // q:[0,512) k:[512,1024)
                const float* rt = g_rope +
                    (size_t)((t >> 13) * LL + ((t >> 3) & (LL - 1))) * 64;
                #pragma unroll
                for (int nf = 0; nf < 4; nf++) {
                    const int j = nf * 8 + q2;
                    const float cs0 = rt[j],     sn0 = rt[32 + j];
                    const float cs1 = rt[j + 1], sn1 = rt[33 + j];
                    const float x0 = v[nf][0], y0 = v[nf + 4][0];
                    const float x1 = v[nf][1], y1 = v[nf + 4][1];
                    v[nf][0]     = x0 * cs0 - y0 * sn0;
                    v[nf + 4][0] = y0 * cs0 + x0 * sn0;
                    v[nf][1]     = x1 * cs1 - y1 * sn1;
                    v[nf + 4][1] = y1 * cs1 + x1 * sn1;
                }
            }
            float* Crow = C + (size_t)t * Nn + gc0;
            #pragma unroll
            for (int nf = 0; nf < 8; nf++) {
                float o0 = v[nf][0], o1 = v[nf][1];
                if (round_store) { o0 = to_tf32(o0); o1 = to_tf32(o1); }
                *(float2*)(Crow + nf * 8 + q2) = make_float2(o0, o1);
            }
        }
    }
}

__global__ __launch_bounds__(256) void qkv_mma_kernel(const float* __restrict__ b_attn)
{
    gemm_v2(g_x, g_wa, b_attn, g_qkv, E3, EE, true, true);
}

__global__ __launch_bounds__(256) void proj_mma_kernel(
    const float* __restrict__ b_proj, float* __restrict__ out)
{
    gemm_v2(g_y, g_wp, b_proj, out, EE, EE, false, false);
}

// ---------------------------------------------------------------------------
// RoPE cos/sin table: [b*L+l][cos j | sin j], j = 0..31
// ---------------------------------------------------------------------------
__global__ __launch_bounds__(256) void rope_table_kernel(const int* __restrict__ pos)
{
    const int i = blockIdx.x * blockDim.x + threadIdx.x;
    if (i >= BB * LL * 32) return;
    const int bl = i >> 5;
    const int j  = i & 31;
    const float p   = (float)pos[bl];
    const float inv = powf(10000.0f, -(float)j / 32.0f);
    float sn, cs;
    sincosf(p * inv, &sn, &cs);
    g_rope[(size_t)bl * 64 + j]      = cs;
    g_rope[(size_t)bl * 64 + 32 + j] = sn;
}

// ---------------------------------------------------------------------------
// Flash attention on tensor cores (tf32 mma.sync, online softmax)
// g_qkv is already tf32-rounded -> staging is a plain copy.
// ---------------------------------------------------------------------------
#define ABQ 64
#define AKV 64
#define KP  68
#define VP  72

__global__ __launch_bounds__(128) void attn_mma_kernel()
{
    __shared__ float sKP[AKV][KP];   // K tile, then P tile
    __shared__ float sV [AKV][VP];   // Q staging, then V

    const int bnh  = blockIdx.y;
    const int h    = bnh & 7;
    const int n    = (bnh >> 3) & 7;
    const int b    = bnh >> 6;
    const int qt   = blockIdx.x;

    const int tid  = threadIdx.x;
    const int lane = tid & 31;
    const int wid  = tid >> 5;
    const int lq   = lane >> 2;
    const int lr   = lane & 3;
    const int w16  = wid * 16;

    for (int i = tid; i < ABQ * 16; i += 128) {
        const int r  = i >> 4;
        const int c4 = (i & 15) << 2;
        *(float4*)&sV[r][c4] = *(const float4*)(g_qkv +
            ((size_t)((b * LL + qt * ABQ + r) * NN + n)) * E3 + h * HD + c4);
    }
    __syncthreads();

    uint32_t aq[8][4];
    #pragma unroll
    for (int ks = 0; ks < 8; ks++) {
        const int k0 = ks * 8;
        aq[ks][0] = __float_as_uint(sV[w16 + lq    ][k0 + lr    ]);
        aq[ks][1] = __float_as_uint(sV[w16 + lq + 8][k0 + lr    ]);
        aq[ks][2] = __float_as_uint(sV[w16 + lq    ][k0 + lr + 4]);
        aq[ks][3] = __float_as_uint(sV[w16 + lq + 8][k0 + lr + 4]);
    }

    float m_run[2] = {-1e30f, -1e30f};
    float l_run[2] = {0.0f, 0.0f};
    float acc[8][4];
    #pragma unroll
    for (int nf = 0; nf < 8; nf++)
        #pragma unroll
        for (int c = 0; c < 4; c++) acc[nf][c] = 0.0f;

    const int nT = qt + 1;
    for (int kt = 0; kt < nT; kt++) {
        __syncthreads();

        for (int i = tid; i < AKV * 16; i += 128) {
            const int r  = i >> 4;
            const int c4 = (i & 15) << 2;
            const float* base = g_qkv +
                ((size_t)((b * LL + kt * AKV + r) * NN + n)) * E3 + h * HD;
            *(float4*)&sKP[r][c4] = *(const float4*)(base + 512 + c4);
            *(float4*)&sV [r][c4] = *(const float4*)(base + 1024 + c4);
        }
        __syncthreads();

        float s[8][4];
        #pragma unroll
        for (int nf = 0; nf < 8; nf++)
            #pragma unroll
            for (int c = 0; c < 4; c++) s[nf][c] = 0.0f;

        #pragma unroll
        for (int ks = 0; ks < 8; ks++) {
            const int k0 = ks * 8;
            #pragma unroll
            for (int nf = 0; nf < 8; nf++) {
                uint32_t bb[2];
                bb[0] = __float_as_uint(sKP[nf * 8 + lq][k0 + lr    ]);
                bb[1] = __float_as_uint(sKP[nf * 8 + lq][k0 + lr + 4]);
                mma_tf32(s[nf], aq[ks], bb);
            }
        }
        __syncthreads();

        const bool diag = (kt == qt);
        const int  r0l  = w16 + lq;
        const int  r1l  = r0l + 8;
        float mx0 = -1e30f, mx1 = -1e30f;
        #pragma unroll
        for (int nf = 0; nf < 8; nf++) {
            #pragma unroll
            for (int c = 0; c < 2; c++) {
                const int col = nf * 8 + 2 * lr + c;
                float v0 = s[nf][c]     * 0.125f;
                float v1 = s[nf][2 + c] * 0.125f;
                if (diag && col > r0l) v0 = -1e30f;
                if (diag && col > r1l) v1 = -1e30f;
                s[nf][c]     = v0;
                s[nf][2 + c] = v1;
                mx0 = fmaxf(mx0, v0);
                mx1 = fmaxf(mx1, v1);
            }
        }
        #pragma unroll
        for (int off = 1; off < 4; off <<= 1) {
            mx0 = fmaxf(mx0, __shfl_xor_sync(0xffffffffu, mx0, off));
            mx1 = fmaxf(mx1, __shfl_xor_sync(0xffffffffu, mx1, off));
        }

        const float mn0 = fmaxf(m_run[0], mx0);
        const float mn1 = fmaxf(m_run[1], mx1);
        const float al0 = __expf(m_run[0] - mn0);
        const float al1 = __expf(m_run[1] - mn1);
        m_run[0] = mn0; m_run[1] = mn1;

        float sum0 = 0.0f, sum1 = 0.0f;
        #pragma unroll
        for (int nf = 0; nf < 8; nf++) {
            const float p00 = __expf(s[nf][0] - mn0);
            const float p01 = __expf(s[nf][1] - mn0);
            const float p10 = __expf(s[nf][2] - mn1);
            const float p11 = __expf(s[nf][3] - mn1);
            sum0 += p00 + p01;
            sum1 += p10 + p11;
            const int cc = nf * 8 + 2 * lr;
            sKP[r0l][cc]     = to_tf32(p00);
            sKP[r0l][cc + 1] = to_tf32(p01);
            sKP[r1l][cc]     = to_tf32(p10);
            sKP[r1l][cc + 1] = to_tf32(p11);
        }
        #pragma unroll
        for (int off = 1; off < 4; off <<= 1) {
            sum0 += __shfl_xor_sync(0xffffffffu, sum0, off);
            sum1 += __shfl_xor_sync(0xffffffffu, sum1, off);
        }
        l_run[0] = l_run[0] * al0 + sum0;
        l_run[1] = l_run[1] * al1 + sum1;

        #pragma unroll
        for (int nf = 0; nf < 8; nf++) {
            acc[nf][0] *= al0; acc[nf][1] *= al0;
            acc[nf][2] *= al1; acc[nf][3] *= al1;
        }
        __syncwarp();

        #pragma unroll
        for (int ks = 0; ks < 8; ks++) {
            const int k0 = ks * 8;
            uint32_t ap[4];
            ap[0] = __float_as_uint(sKP[r0l][k0 + lr    ]);
            ap[1] = __float_as_uint(sKP[r1l][k0 + lr    ]);
            ap[2] = __float_as_uint(sKP[r0l][k0 + lr + 4]);
            ap[3] = __float_as_uint(sKP[r1l][k0 + lr + 4]);
            #pragma unroll
            for (int nf = 0; nf < 8; nf++) {
                uint32_t bb[2];
                bb[0] = __float_as_uint(sV[k0 + lr    ][nf * 8 + lq]);
                bb[1] = __float_as_uint(sV[k0 + lr + 4][nf * 8 + lq]);
                mma_tf32(acc[nf], ap, bb);
            }
        }
    }

    const float inv0 = 1.0f / l_run[0];
    const float inv1 = 1.0f / l_run[1];
    const int gr0 = qt * ABQ + w16 + lq;
    const int gr1 = gr0 + 8;
    float* y0 = g_y + ((size_t)((b * LL + gr0) * NN + n)) * EE + h * HD;
    float* y1 = g_y + ((size_t)((b * LL + gr1) * NN + n)) * EE + h * HD;
    #pragma unroll
    for (int nf = 0; nf < 8; nf++) {
        const int cc = nf * 8 + 2 * lr;
        *(float2*)(y0 + cc) = make_float2(to_tf32(acc[nf][0] * inv0),
                                          to_tf32(acc[nf][1] * inv0));
        *(float2*)(y1 + cc) = make_float2(to_tf32(acc[nf][2] * inv1),
                                          to_tf32(acc[nf][3] * inv1));
    }
}

// ---------------------------------------------------------------------------
// launch
// ---------------------------------------------------------------------------
extern "C" void kernel_launch(void* const* d_in, const int* in_sizes, int n_in,
                              void* d_out, int out_size)
{
    const float* x      = (const float*)d_in[0];
    const int*   pos    = (const int*)  d_in[1];
    const float* w_attn = (const float*)d_in[2];
    const float* b_attn = (const float*)d_in[3];
    const float* w_proj = (const float*)d_in[4];
    const float* b_proj = (const float*)d_in[5];
    float*       out    = (float*)d_out;

    // 0) pre-round inputs/weights to tf32 (dst symbols referenced in-kernel)
    cvt_x_kernel <<<(MTOK * EE / 4 + 255) / 256, 256>>>(x);
    cvt_wa_kernel<<<(EE * E3 / 4 + 255) / 256, 256>>>(w_attn);
    cvt_wp_kernel<<<(EE * EE / 4 + 255) / 256, 256>>>(w_proj);

    // 1) cos/sin table
    rope_table_kernel<<<(BB * LL * 32) / 256, 256>>>(pos);

    // 2) QKV tf32 GEMM (cp.async 2-stage) + fused bias + RoPE, tf32 store
    qkv_mma_kernel<<<dim3(E3 / 128, MTOK / 128), 256>>>(b_attn);

    // 3) causal flash attention on tensor cores -> g_y (tf32 store)
    attn_mma_kernel<<<dim3(LL / ABQ, BB * NN * HH), 128>>>();

    // 4) out = y @ w_proj + b_proj (fp32 store)
    proj_mma_kernel<<<dim3(EE / 128, MTOK / 128), 256>>>(b_proj, out);
}

// round 8
// speedup vs baseline: 3.3820x; 1.1146x over previous
#include <cuda_runtime.h>
#include <math.h>
#include <stdint.h>

// Problem dims (fixed by the dataset)
#define BB    2
#define LL    1024
#define NN    8
#define EE    512
#define HH    8
#define HD    64
#define E3    1536
#define MTOK  (BB * LL * NN)          // 16384 tokens

// ---------------------------------------------------------------------------
// Scratch (device globals)
// ---------------------------------------------------------------------------
__device__ float g_qkv [(size_t)MTOK * E3];     // [token][1536] q|k|v (tf32, post-RoPE)
__device__ float g_y   [(size_t)MTOK * EE];     // attention out (tf32)
__device__ float g_rope[(size_t)BB * LL * 64];  // [b*L+l][cos32|sin32]
__device__ float g_x   [(size_t)MTOK * EE];     // x pre-rounded to tf32
__device__ float g_wa  [(size_t)EE * E3];       // w_attn tf32
__device__ float g_wp  [(size_t)EE * EE];       // w_proj tf32

// ---------------------------------------------------------------------------
// helpers
// ---------------------------------------------------------------------------
__device__ __forceinline__ float to_tf32(float x) {
    uint32_t o;
    asm("cvt.rna.tf32.f32 %0, %1;" : "=r"(o) : "f"(x));
    return __uint_as_float(o);
}

__device__ __forceinline__ void mma_tf32(float* c, const uint32_t* a,
                                         const uint32_t* b) {
    asm volatile(
        "mma.sync.aligned.m16n8k8.row.col.f32.tf32.tf32.f32 "
        "{%0,%1,%2,%3}, {%4,%5,%6,%7}, {%8,%9}, {%0,%1,%2,%3};"
        : "+f"(c[0]), "+f"(c[1]), "+f"(c[2]), "+f"(c[3])
        : "r"(a[0]), "r"(a[1]), "r"(a[2]), "r"(a[3]), "r"(b[0]), "r"(b[1]));
}

__device__ __forceinline__ void cp16(void* smem, const void* gmem) {
    uint32_t s = (uint32_t)__cvta_generic_to_shared(smem);
    asm volatile("cp.async.ca.shared.global [%0], [%1], 16;" :: "r"(s), "l"(gmem));
}
#define CP_COMMIT() asm volatile("cp.async.commit_group;" ::)
#define CP_WAIT1()  asm volatile("cp.async.wait_group 1;" ::: "memory")

// ---------------------------------------------------------------------------
// elementwise tf32 pre-rounding (dst = __device__ symbols, no host symbol API)
// ---------------------------------------------------------------------------
__device__ __forceinline__ void cvt_body(const float* __restrict__ s,
                                         float* __restrict__ d, int n)
{
    const int i = (blockIdx.x * blockDim.x + threadIdx.x) << 2;
    if (i >= n) return;
    float4 v = *(const float4*)(s + i);
    v.x = to_tf32(v.x); v.y = to_tf32(v.y);
    v.z = to_tf32(v.z); v.w = to_tf32(v.w);
    *(float4*)(d + i) = v;
}
__global__ __launch_bounds__(256) void cvt_x_kernel (const float* __restrict__ s)
{ cvt_body(s, g_x,  MTOK * EE); }
__global__ __launch_bounds__(256) void cvt_wa_kernel(const float* __restrict__ s)
{ cvt_body(s, g_wa, EE * E3); }
__global__ __launch_bounds__(256) void cvt_wp_kernel(const float* __restrict__ s)
{ cvt_body(s, g_wp, EE * EE); }

// ---------------------------------------------------------------------------
// cp.async double-buffered tf32 GEMM: C[128m x 128n] per CTA.
// 128 thr = 4 warps (2M x 2N), warp tile 64x64 (4x8 m16n8k8 frags), KC=16/stage.
// LDS/mma ratio 1.0 (16+16 LDS per 32 mma). Inputs already tf32-rounded.
//   sA[st][row][k]: pitch 20 -> frag bank = (20*lq+lr)%32 bijective, no conflict
//   sB[st][k][n]:   pitch 132 -> frag bank = (4*lr+lq)%32 bijective, no conflict
// ---------------------------------------------------------------------------
#define KC2 16
#define PA  20
#define PB  132

__device__ __forceinline__ void gemm_v3(
    const float* __restrict__ A, const float* __restrict__ W,
    const float* __restrict__ bias, float* __restrict__ C,
    int Nn, int K, bool do_rope, bool round_store)
{
    __shared__ float sA[2][128][PA];   // 20.0 KB
    __shared__ float sB[2][KC2][PB];   // 16.5 KB

    const int tid   = threadIdx.x;     // 0..127
    const int lane  = tid & 31;
    const int wid   = tid >> 5;        // 0..3
    const int warpM = wid & 1;         // 0..1 -> 64 rows
    const int warpN = wid >> 1;        // 0..1 -> 64 cols
    const int lq    = lane >> 2;       // 0..7
    const int lr    = lane & 3;        // 0..3

    const int m0 = blockIdx.y * 128;
    const int n0 = blockIdx.x * 128;

    float acc[4][8][4];
    #pragma unroll
    for (int i = 0; i < 4; i++)
        #pragma unroll
        for (int j = 0; j < 8; j++)
            #pragma unroll
            for (int c = 0; c < 4; c++) acc[i][j][c] = 0.0f;

    const int nch = K / KC2;

    // ---- prefetch stage 0 ----
    {
        #pragma unroll
        for (int it = 0; it < 4; it++) {
            const int i   = tid + it * 128;     // 0..511
            const int row = i >> 2;
            const int c4  = (i & 3) << 2;
            cp16(&sA[0][row][c4], A + (size_t)(m0 + row) * K + c4);
        }
        #pragma unroll
        for (int it = 0; it < 4; it++) {
            const int i  = tid + it * 128;
            const int kk = i >> 5;
            const int n4 = (i & 31) << 2;
            cp16(&sB[0][kk][n4], W + (size_t)kk * Nn + n0 + n4);
        }
        CP_COMMIT();
    }

    for (int ch = 0; ch < nch; ch++) {
        if (ch + 1 < nch) {
            const int st = (ch + 1) & 1;
            const int k0 = (ch + 1) * KC2;
            #pragma unroll
            for (int it = 0; it < 4; it++) {
                const int i   = tid + it * 128;
                const int row = i >> 2;
                const int c4  = (i & 3) << 2;
                cp16(&sA[st][row][c4], A + (size_t)(m0 + row) * K + k0 + c4);
            }
            #pragma unroll
            for (int it = 0; it < 4; it++) {
                const int i  = tid + it * 128;
                const int kk = i >> 5;
                const int n4 = (i & 31) << 2;
                cp16(&sB[st][kk][n4], W + (size_t)(k0 + kk) * Nn + n0 + n4);
            }
        }
        CP_COMMIT();
        CP_WAIT1();            // stage ch resident
        __syncthreads();

        const int st = ch & 1;
        #pragma unroll
        for (int s = 0; s < 2; s++) {
            const int s8 = s * 8;
            uint32_t af[4][4], bf[8][2];
            #pragma unroll
            for (int mf = 0; mf < 4; mf++) {
                const int mr = warpM * 64 + mf * 16;
                af[mf][0] = __float_as_uint(sA[st][mr + lq    ][s8 + lr    ]);
                af[mf][1] = __float_as_uint(sA[st][mr + lq + 8][s8 + lr    ]);
                af[mf][2] = __float_as_uint(sA[st][mr + lq    ][s8 + lr + 4]);
                af[mf][3] = __float_as_uint(sA[st][mr + lq + 8][s8 + lr + 4]);
            }
            #pragma unroll
            for (int nf = 0; nf < 8; nf++) {
                const int nb = warpN * 64 + nf * 8 + lq;
                bf[nf][0] = __float_as_uint(sB[st][s8 + lr    ][nb]);
                bf[nf][1] = __float_as_uint(sB[st][s8 + lr + 4][nb]);
            }
            #pragma unroll
            for (int mf = 0; mf < 4; mf++)
                #pragma unroll
                for (int nf = 0; nf < 8; nf++)
                    mma_tf32(acc[mf][nf], af[mf], bf[nf]);
        }
        __syncthreads();       // all warps done before buffer reuse
    }

    // ---- epilogue ----
    const int gc0 = n0 + warpN * 64;    // head-aligned 64-col block
    const int q2  = lr * 2;

    float b0[8], b1[8];
    #pragma unroll
    for (int nf = 0; nf < 8; nf++) {
        b0[nf] = bias[gc0 + nf * 8 + q2];
        b1[nf] = bias[gc0 + nf * 8 + q2 + 1];
    }

    #pragma unroll
    for (int mf = 0; mf < 4; mf++) {
        #pragma unroll
        for (int rs = 0; rs < 2; rs++) {
            const int row = warpM * 64 + mf * 16 + lq + rs * 8;
            const int t   = m0 + row;
            float v[8][2];
            #pragma unroll
            for (int nf = 0; nf < 8; nf++) {
                v[nf][0] = acc[mf][nf][rs * 2]     + b0[nf];
                v[nf][1] = acc[mf][nf][rs * 2 + 1] + b1[nf];
            }
            if (do_rope && gc0 < 1024) {    // q:[0,512) k:[512,1024)
                const float* rt = g_rope +
                    (size_t)((t >> 13) * LL + ((t >> 3) & (LL - 1))) * 64;
                #pragma unroll
                for (int nf = 0; nf < 4; nf++) {
                    const int j = nf * 8 + q2;
                    const float cs0 = rt[j],     sn0 = rt[32 + j];
                    const float cs1 = rt[j + 1], sn1 = rt[33 + j];
                    const float x0 = v[nf][0], y0 = v[nf + 4][0];
                    const float x1 = v[nf][1], y1 = v[nf + 4][1];
                    v[nf][0]     = x0 * cs0 - y0 * sn0;
                    v[nf + 4][0] = y0 * cs0 + x0 * sn0;
                    v[nf][1]     = x1 * cs1 - y1 * sn1;
                    v[nf + 4][1] = y1 * cs1 + x1 * sn1;
                }
            }
            float* Crow = C + (size_t)t * Nn + gc0;
            #pragma unroll
            for (int nf = 0; nf < 8; nf++) {
                float o0 = v[nf][0], o1 = v[nf][1];
                if (round_store) { o0 = to_tf32(o0); o1 = to_tf32(o1); }
                *(float2*)(Crow + nf * 8 + q2) = make_float2(o0, o1);
            }
        }
    }
}

__global__ __launch_bounds__(128) void qkv_mma_kernel(const float* __restrict__ b_attn)
{
    gemm_v3(g_x, g_wa, b_attn, g_qkv, E3, EE, true, true);
}

__global__ __launch_bounds__(128) void proj_mma_kernel(
    const float* __restrict__ b_proj, float* __restrict__ out)
{
    gemm_v3(g_y, g_wp, b_proj, out, EE, EE, false, false);
}

// ---------------------------------------------------------------------------
// RoPE cos/sin table: [b*L+l][cos j | sin j], j = 0..31
// ---------------------------------------------------------------------------
__global__ __launch_bounds__(256) void rope_table_kernel(const int* __restrict__ pos)
{
    const int i = blockIdx.x * blockDim.x + threadIdx.x;
    if (i >= BB * LL * 32) return;
    const int bl = i >> 5;
    const int j  = i & 31;
    const float p   = (float)pos[bl];
    const float inv = powf(10000.0f, -(float)j / 32.0f);
    float sn, cs;
    sincosf(p * inv, &sn, &cs);
    g_rope[(size_t)bl * 64 + j]      = cs;
    g_rope[(size_t)bl * 64 + 32 + j] = sn;
}

// ---------------------------------------------------------------------------
// Flash attention on tensor cores (tf32 mma.sync, online softmax)
// g_qkv is already tf32-rounded -> staging is a plain copy.
// ---------------------------------------------------------------------------
#define ABQ 64
#define AKV 64
#define KP  68
#define VP  72

__global__ __launch_bounds__(128) void attn_mma_kernel()
{
    __shared__ float sKP[AKV][KP];   // K tile, then P tile
    __shared__ float sV [AKV][VP];   // Q staging, then V

    const int bnh  = blockIdx.y;
    const int h    = bnh & 7;
    const int n    = (bnh >> 3) & 7;
    const int b    = bnh >> 6;
    const int qt   = blockIdx.x;

    const int tid  = threadIdx.x;
    const int lane = tid & 31;
    const int wid  = tid >> 5;
    const int lq   = lane >> 2;
    const int lr   = lane & 3;
    const int w16  = wid * 16;

    for (int i = tid; i < ABQ * 16; i += 128) {
        const int r  = i >> 4;
        const int c4 = (i & 15) << 2;
        *(float4*)&sV[r][c4] = *(const float4*)(g_qkv +
            ((size_t)((b * LL + qt * ABQ + r) * NN + n)) * E3 + h * HD + c4);
    }
    __syncthreads();

    uint32_t aq[8][4];
    #pragma unroll
    for (int ks = 0; ks < 8; ks++) {
        const int k0 = ks * 8;
        aq[ks][0] = __float_as_uint(sV[w16 + lq    ][k0 + lr    ]);
        aq[ks][1] = __float_as_uint(sV[w16 + lq + 8][k0 + lr    ]);
        aq[ks][2] = __float_as_uint(sV[w16 + lq    ][k0 + lr + 4]);
        aq[ks][3] = __float_as_uint(sV[w16 + lq + 8][k0 + lr + 4]);
    }

    float m_run[2] = {-1e30f, -1e30f};
    float l_run[2] = {0.0f, 0.0f};
    float acc[8][4];
    #pragma unroll
    for (int nf = 0; nf < 8; nf++)
        #pragma unroll
        for (int c = 0; c < 4; c++) acc[nf][c] = 0.0f;

    const int nT = qt + 1;
    for (int kt = 0; kt < nT; kt++) {
        __syncthreads();

        for (int i = tid; i < AKV * 16; i += 128) {
            const int r  = i >> 4;
            const int c4 = (i & 15) << 2;
            const float* base = g_qkv +
                ((size_t)((b * LL + kt * AKV + r) * NN + n)) * E3 + h * HD;
            *(float4*)&sKP[r][c4] = *(const float4*)(base + 512 + c4);
            *(float4*)&sV [r][c4] = *(const float4*)(base + 1024 + c4);
        }
        __syncthreads();

        float s[8][4];
        #pragma unroll
        for (int nf = 0; nf < 8; nf++)
            #pragma unroll
            for (int c = 0; c < 4; c++) s[nf][c] = 0.0f;

        #pragma unroll
        for (int ks = 0; ks < 8; ks++) {
            const int k0 = ks * 8;
            #pragma unroll
            for (int nf = 0; nf < 8; nf++) {
                uint32_t bb[2];
                bb[0] = __float_as_uint(sKP[nf * 8 + lq][k0 + lr    ]);
                bb[1] = __float_as_uint(sKP[nf * 8 + lq][k0 + lr + 4]);
                mma_tf32(s[nf], aq[ks], bb);
            }
        }
        __syncthreads();

        const bool diag = (kt == qt);
        const int  r0l  = w16 + lq;
        const int  r1l  = r0l + 8;
        float mx0 = -1e30f, mx1 = -1e30f;
        #pragma unroll
        for (int nf = 0; nf < 8; nf++) {
            #pragma unroll
            for (int c = 0; c < 2; c++) {
                const int col = nf * 8 + 2 * lr + c;
                float v0 = s[nf][c]     * 0.125f;
                float v1 = s[nf][2 + c] * 0.125f;
                if (diag && col > r0l) v0 = -1e30f;
                if (diag && col > r1l) v1 = -1e30f;
                s[nf][c]     = v0;
                s[nf][2 + c] = v1;
                mx0 = fmaxf(mx0, v0);
                mx1 = fmaxf(mx1, v1);
            }
        }
        #pragma unroll
        for (int off = 1; off < 4; off <<= 1) {
            mx0 = fmaxf(mx0, __shfl_xor_sync(0xffffffffu, mx0, off));
            mx1 = fmaxf(mx1, __shfl_xor_sync(0xffffffffu, mx1, off));
        }

        const float mn0 = fmaxf(m_run[0], mx0);
        const float mn1 = fmaxf(m_run[1], mx1);
        const float al0 = __expf(m_run[0] - mn0);
        const float al1 = __expf(m_run[1] - mn1);
        m_run[0] = mn0; m_run[1] = mn1;

        float sum0 = 0.0f, sum1 = 0.0f;
        #pragma unroll
        for (int nf = 0; nf < 8; nf++) {
            const float p00 = __expf(s[nf][0] - mn0);
            const float p01 = __expf(s[nf][1] - mn0);
            const float p10 = __expf(s[nf][2] - mn1);
            const float p11 = __expf(s[nf][3] - mn1);
            sum0 += p00 + p01;
            sum1 += p10 + p11;
            const int cc = nf * 8 + 2 * lr;
            sKP[r0l][cc]     = to_tf32(p00);
            sKP[r0l][cc + 1] = to_tf32(p01);
            sKP[r1l][cc]     = to_tf32(p10);
            sKP[r1l][cc + 1] = to_tf32(p11);
        }
        #pragma unroll
        for (int off = 1; off < 4; off <<= 1) {
            sum0 += __shfl_xor_sync(0xffffffffu, sum0, off);
            sum1 += __shfl_xor_sync(0xffffffffu, sum1, off);
        }
        l_run[0] = l_run[0] * al0 + sum0;
        l_run[1] = l_run[1] * al1 + sum1;

        #pragma unroll
        for (int nf = 0; nf < 8; nf++) {
            acc[nf][0] *= al0; acc[nf][1] *= al0;
            acc[nf][2] *= al1; acc[nf][3] *= al1;
        }
        __syncwarp();

        #pragma unroll
        for (int ks = 0; ks < 8; ks++) {
            const int k0 = ks * 8;
            uint32_t ap[4];
            ap[0] = __float_as_uint(sKP[r0l][k0 + lr    ]);
            ap[1] = __float_as_uint(sKP[r1l][k0 + lr    ]);
            ap[2] = __float_as_uint(sKP[r0l][k0 + lr + 4]);
            ap[3] = __float_as_uint(sKP[r1l][k0 + lr + 4]);
            #pragma unroll
            for (int nf = 0; nf < 8; nf++) {
                uint32_t bb[2];
                bb[0] = __float_as_uint(sV[k0 + lr    ][nf * 8 + lq]);
                bb[1] = __float_as_uint(sV[k0 + lr + 4][nf * 8 + lq]);
                mma_tf32(acc[nf], ap, bb);
            }
        }
    }

    const float inv0 = 1.0f / l_run[0];
    const float inv1 = 1.0f / l_run[1];
    const int gr0 = qt * ABQ + w16 + lq;
    const int gr1 = gr0 + 8;
    float* y0 = g_y + ((size_t)((b * LL + gr0) * NN + n)) * EE + h * HD;
    float* y1 = g_y + ((size_t)((b * LL + gr1) * NN + n)) * EE + h * HD;
    #pragma unroll
    for (int nf = 0; nf < 8; nf++) {
        const int cc = nf * 8 + 2 * lr;
        *(float2*)(y0 + cc) = make_float2(to_tf32(acc[nf][0] * inv0),
                                          to_tf32(acc[nf][1] * inv0));
        *(float2*)(y1 + cc) = make_float2(to_tf32(acc[nf][2] * inv1),
                                          to_tf32(acc[nf][3] * inv1));
    }
}

// ---------------------------------------------------------------------------
// launch
// ---------------------------------------------------------------------------
extern "C" void kernel_launch(void* const* d_in, const int* in_sizes, int n_in,
                              void* d_out, int out_size)
{
    const float* x      = (const float*)d_in[0];
    const int*   pos    = (const int*)  d_in[1];
    const float* w_attn = (const float*)d_in[2];
    const float* b_attn = (const float*)d_in[3];
    const float* w_proj = (const float*)d_in[4];
    const float* b_proj = (const float*)d_in[5];
    float*       out    = (float*)d_out;

    // 0) pre-round inputs/weights to tf32
    cvt_x_kernel <<<(MTOK * EE / 4 + 255) / 256, 256>>>(x);
    cvt_wa_kernel<<<(EE * E3 / 4 + 255) / 256, 256>>>(w_attn);
    cvt_wp_kernel<<<(EE * EE / 4 + 255) / 256, 256>>>(w_proj);

    // 1) cos/sin table
    rope_table_kernel<<<(BB * LL * 32) / 256, 256>>>(pos);

    // 2) QKV tf32 GEMM (4-warp, 64x64 warp tile) + fused bias + RoPE
    qkv_mma_kernel<<<dim3(E3 / 128, MTOK / 128), 128>>>(b_attn);

    // 3) causal flash attention on tensor cores -> g_y (tf32 store)
    attn_mma_kernel<<<dim3(LL / ABQ, BB * NN * HH), 128>>>();

    // 4) out = y @ w_proj + b_proj (fp32 store)
    proj_mma_kernel<<<dim3(EE / 128, MTOK / 128), 128>>>(b_proj, out);
}